// round 1
// baseline (speedup 1.0000x reference)
#include <cuda_runtime.h>

// Problem constants (fixed by setup_inputs)
#define N_PTS  4096
#define M_PTS  16384
#define C_IN   256
#define C_SKIP 128
#define C_CAT  384
#define H_DIM  256

// Scratch (device globals — no runtime allocation allowed)
__device__ float g_feat[M_PTS * C_CAT];   // [M, 384] concat(y, x_skip)
__device__ float g_h[M_PTS * H_DIM];      // [M, 256] hidden
__device__ int   g_idx[M_PTS * 3];
__device__ float g_w[M_PTS * 4];          // w0,w1,w2, 1/(w0+w1+w2)

// ---------------------------------------------------------------------------
// Kernel 1: brute-force kNN (k=3). One thread per query; pos tiled in smem.
// ---------------------------------------------------------------------------
#define KNN_TILE 2048
__global__ void knn_kernel(const float* __restrict__ pos,
                           const float* __restrict__ pos_skip) {
    __shared__ float sx[KNN_TILE], sy[KNN_TILE], sz[KNN_TILE];
    int m = blockIdx.x * blockDim.x + threadIdx.x;
    float qx = 0.f, qy = 0.f, qz = 0.f;
    if (m < M_PTS) {
        qx = pos_skip[3 * m + 0];
        qy = pos_skip[3 * m + 1];
        qz = pos_skip[3 * m + 2];
    }
    float d0 = 1e30f, d1 = 1e30f, d2 = 1e30f;
    int   i0 = 0, i1 = 0, i2 = 0;

    for (int base = 0; base < N_PTS; base += KNN_TILE) {
        __syncthreads();
        for (int j = threadIdx.x; j < KNN_TILE; j += blockDim.x) {
            sx[j] = pos[3 * (base + j) + 0];
            sy[j] = pos[3 * (base + j) + 1];
            sz[j] = pos[3 * (base + j) + 2];
        }
        __syncthreads();
        #pragma unroll 4
        for (int j = 0; j < KNN_TILE; j++) {
            float dx = qx - sx[j];
            float dy = qy - sy[j];
            float dz = qz - sz[j];
            float d = fmaf(dx, dx, fmaf(dy, dy, dz * dz));
            int gi = base + j;
            if (d < d2) {
                if (d < d1) {
                    d2 = d1; i2 = i1;
                    if (d < d0) { d1 = d0; i1 = i0; d0 = d; i0 = gi; }
                    else        { d1 = d;  i1 = gi; }
                } else { d2 = d; i2 = gi; }
            }
        }
    }

    if (m < M_PTS) {
        float w0 = 1.f / fmaxf(d0, 1e-16f);
        float w1 = 1.f / fmaxf(d1, 1e-16f);
        float w2 = 1.f / fmaxf(d2, 1e-16f);
        g_idx[3 * m + 0] = i0;
        g_idx[3 * m + 1] = i1;
        g_idx[3 * m + 2] = i2;
        g_w[4 * m + 0] = w0;
        g_w[4 * m + 1] = w1;
        g_w[4 * m + 2] = w2;
        g_w[4 * m + 3] = 1.f / (w0 + w1 + w2);
    }
}

// ---------------------------------------------------------------------------
// Kernel 2: interpolate + concat -> g_feat [M, 384]
// One block per query row, 384 threads (one per output channel).
// ---------------------------------------------------------------------------
__global__ void interp_kernel(const float* __restrict__ x,
                              const float* __restrict__ x_skip) {
    int m = blockIdx.x;
    int c = threadIdx.x;
    __shared__ int   si[3];
    __shared__ float sw[4];
    if (threadIdx.x < 3) si[threadIdx.x] = g_idx[3 * m + threadIdx.x];
    if (threadIdx.x >= 4 && threadIdx.x < 8)
        sw[threadIdx.x - 4] = g_w[4 * m + (threadIdx.x - 4)];
    __syncthreads();
    if (c < C_IN) {
        float y = sw[0] * x[si[0] * C_IN + c]
                + sw[1] * x[si[1] * C_IN + c]
                + sw[2] * x[si[2] * C_IN + c];
        g_feat[m * C_CAT + c] = y * sw[3];
    } else {
        g_feat[m * C_CAT + c] = x_skip[m * C_SKIP + (c - C_IN)];
    }
}

// ---------------------------------------------------------------------------
// Kernel 3/4: tiled SGEMM  C = relu?(A[M,K] @ B[K,N] + bias)
// BM=64, BN=64, BK=16, 256 threads, 4x4 per thread.
// ---------------------------------------------------------------------------
template <int KDIM, bool RELU>
__global__ void gemm_kernel(const float* __restrict__ A,
                            const float* __restrict__ B,
                            const float* __restrict__ bias,
                            float* __restrict__ C,
                            int Mrows, int Ncols) {
    const int BM = 64, BN = 64, BK = 16;
    __shared__ float As[BK][BM + 4];
    __shared__ float Bs[BK][BN + 4];

    int row0 = blockIdx.x * BM;
    int col0 = blockIdx.y * BN;
    int tid = threadIdx.x;
    int ty = tid / 16;          // 0..15
    int tx = tid % 16;          // 0..15

    float acc[4][4];
    #pragma unroll
    for (int i = 0; i < 4; i++)
        #pragma unroll
        for (int j = 0; j < 4; j++) acc[i][j] = 0.f;

    for (int k0 = 0; k0 < KDIM; k0 += BK) {
        // Load A tile: 64x16 = 1024 elements, 4 per thread
        #pragma unroll
        for (int l = 0; l < 4; l++) {
            int e = tid + l * 256;
            int mi = e / BK;
            int ki = e % BK;
            As[ki][mi] = A[(row0 + mi) * KDIM + (k0 + ki)];
        }
        // Load B tile: 16x64 = 1024 elements, 4 per thread
        #pragma unroll
        for (int l = 0; l < 4; l++) {
            int e = tid + l * 256;
            int ki = e / BN;
            int ni = e % BN;
            Bs[ki][ni] = B[(k0 + ki) * Ncols + (col0 + ni)];
        }
        __syncthreads();

        #pragma unroll
        for (int kk = 0; kk < BK; kk++) {
            float a[4], b[4];
            #pragma unroll
            for (int i = 0; i < 4; i++) a[i] = As[kk][ty * 4 + i];
            #pragma unroll
            for (int j = 0; j < 4; j++) b[j] = Bs[kk][tx * 4 + j];
            #pragma unroll
            for (int i = 0; i < 4; i++)
                #pragma unroll
                for (int j = 0; j < 4; j++)
                    acc[i][j] = fmaf(a[i], b[j], acc[i][j]);
        }
        __syncthreads();
    }

    #pragma unroll
    for (int i = 0; i < 4; i++) {
        int r = row0 + ty * 4 + i;
        #pragma unroll
        for (int j = 0; j < 4; j++) {
            int cidx = col0 + tx * 4 + j;
            float v = acc[i][j] + bias[cidx];
            if (RELU) v = fmaxf(v, 0.f);
            C[r * Ncols + cidx] = v;
        }
    }
}

// ---------------------------------------------------------------------------
// Kernel 5: tail of output — copy pos_skip, zero the batch segment
// ---------------------------------------------------------------------------
__global__ void tail_kernel(const float* __restrict__ pos_skip,
                            float* __restrict__ out, int out_size) {
    const int base = M_PTS * H_DIM;
    for (int i = base + blockIdx.x * blockDim.x + threadIdx.x; i < out_size;
         i += gridDim.x * blockDim.x) {
        int r = i - base;
        out[i] = (r < M_PTS * 3) ? pos_skip[r] : 0.f;
    }
}

// ---------------------------------------------------------------------------
extern "C" void kernel_launch(void* const* d_in, const int* in_sizes, int n_in,
                              void* d_out, int out_size) {
    const float* x        = (const float*)d_in[0];
    const float* pos      = (const float*)d_in[1];
    // d_in[2] = batch (int64, all zeros — unused)
    const float* x_skip   = (const float*)d_in[3];
    const float* pos_skip = (const float*)d_in[4];
    // d_in[5] = batch_skip (int64, all zeros — unused)
    const float* W1 = (const float*)d_in[6];
    const float* b1 = (const float*)d_in[7];
    const float* W2 = (const float*)d_in[8];
    const float* b2 = (const float*)d_in[9];
    float* out = (float*)d_out;

    // 1) kNN
    knn_kernel<<<M_PTS / 256, 256>>>(pos, pos_skip);

    // 2) interpolate + concat
    interp_kernel<<<M_PTS, C_CAT>>>(x, x_skip);

    // 3) GEMM1 + ReLU: [M,384] @ [384,256] -> g_h
    {
        float* feat;  cudaGetSymbolAddress((void**)&feat, g_feat);
        float* h;     cudaGetSymbolAddress((void**)&h, g_h);
        dim3 grid(M_PTS / 64, H_DIM / 64);
        gemm_kernel<C_CAT, true><<<grid, 256>>>(feat, W1, b1, h, M_PTS, H_DIM);
        // 4) GEMM2: [M,256] @ [256,256] -> out[0 : M*256]
        gemm_kernel<H_DIM, false><<<grid, 256>>>(h, W2, b2, out, M_PTS, H_DIM);
    }

    // 5) tail: pos_skip copy + zeros for batch segment
    tail_kernel<<<256, 256>>>(pos_skip, out, out_size);
}

// round 2
// speedup vs baseline: 1.5743x; 1.5743x over previous
#include <cuda_runtime.h>

#define N_PTS  4096
#define M_PTS  16384
#define C_IN   256
#define C_SKIP 128
#define C_CAT  384
#define H_DIM  256

// Scratch (device globals — no runtime allocation allowed)
__device__ float g_feat[M_PTS * C_CAT];   // [M, 384] concat(y, x_skip)
__device__ float g_h[M_PTS * H_DIM];      // [M, 256] hidden
__device__ int   g_idx[M_PTS * 3];
__device__ float g_w[M_PTS * 4];          // w0,w1,w2, 1/(w0+w1+w2)

// ---------------------------------------------------------------------------
// Kernel 1: brute-force kNN (k=3). 8 threads per query, 32 queries per block.
// ---------------------------------------------------------------------------
#define KNN_TILE 1024
#define QPB 32
#define TPQ 8
__global__ void knn_kernel(const float* __restrict__ pos,
                           const float* __restrict__ pos_skip) {
    __shared__ float sx[KNN_TILE], sy[KNN_TILE], sz[KNN_TILE];
    __shared__ float pd[QPB][TPQ][3];
    __shared__ int   pi[QPB][TPQ][3];

    int qi = threadIdx.x / TPQ;      // 0..31 query slot in block
    int ts = threadIdx.x % TPQ;      // 0..7 sub-thread
    int m  = blockIdx.x * QPB + qi;

    float qx = pos_skip[3 * m + 0];
    float qy = pos_skip[3 * m + 1];
    float qz = pos_skip[3 * m + 2];

    float d0 = 1e30f, d1 = 1e30f, d2 = 1e30f;
    int   i0 = 0, i1 = 0, i2 = 0;

    for (int base = 0; base < N_PTS; base += KNN_TILE) {
        __syncthreads();
        for (int j = threadIdx.x; j < KNN_TILE; j += blockDim.x) {
            sx[j] = pos[3 * (base + j) + 0];
            sy[j] = pos[3 * (base + j) + 1];
            sz[j] = pos[3 * (base + j) + 2];
        }
        __syncthreads();
        #pragma unroll 8
        for (int j = ts; j < KNN_TILE; j += TPQ) {
            float dx = qx - sx[j];
            float dy = qy - sy[j];
            float dz = qz - sz[j];
            float d = fmaf(dx, dx, fmaf(dy, dy, dz * dz));
            int gi = base + j;
            if (d < d2) {
                if (d < d1) {
                    d2 = d1; i2 = i1;
                    if (d < d0) { d1 = d0; i1 = i0; d0 = d; i0 = gi; }
                    else        { d1 = d;  i1 = gi; }
                } else { d2 = d; i2 = gi; }
            }
        }
    }

    pd[qi][ts][0] = d0; pd[qi][ts][1] = d1; pd[qi][ts][2] = d2;
    pi[qi][ts][0] = i0; pi[qi][ts][1] = i1; pi[qi][ts][2] = i2;
    __syncthreads();

    if (ts == 0) {
        float b0 = 1e30f, b1 = 1e30f, b2 = 1e30f;
        int   j0 = 0, j1 = 0, j2 = 0;
        #pragma unroll
        for (int t = 0; t < TPQ; t++) {
            #pragma unroll
            for (int s = 0; s < 3; s++) {
                float d = pd[qi][t][s];
                int   gi = pi[qi][t][s];
                if (d < b2) {
                    if (d < b1) {
                        b2 = b1; j2 = j1;
                        if (d < b0) { b1 = b0; j1 = j0; b0 = d; j0 = gi; }
                        else        { b1 = d;  j1 = gi; }
                    } else { b2 = d; j2 = gi; }
                }
            }
        }
        float w0 = 1.f / fmaxf(b0, 1e-16f);
        float w1 = 1.f / fmaxf(b1, 1e-16f);
        float w2 = 1.f / fmaxf(b2, 1e-16f);
        g_idx[3 * m + 0] = j0;
        g_idx[3 * m + 1] = j1;
        g_idx[3 * m + 2] = j2;
        g_w[4 * m + 0] = w0;
        g_w[4 * m + 1] = w1;
        g_w[4 * m + 2] = w2;
        g_w[4 * m + 3] = 1.f / (w0 + w1 + w2);
    }
}

// ---------------------------------------------------------------------------
// Kernel 2: interpolate + concat -> g_feat [M, 384]. One warp per row, float4.
// ---------------------------------------------------------------------------
__global__ void interp_kernel(const float* __restrict__ x,
                              const float* __restrict__ x_skip) {
    int warp = (blockIdx.x * blockDim.x + threadIdx.x) >> 5;
    int lane = threadIdx.x & 31;
    if (warp >= M_PTS) return;
    int m = warp;

    int i0 = g_idx[3 * m + 0];
    int i1 = g_idx[3 * m + 1];
    int i2 = g_idx[3 * m + 2];
    float w0 = g_w[4 * m + 0];
    float w1 = g_w[4 * m + 1];
    float w2 = g_w[4 * m + 2];
    float inv = g_w[4 * m + 3];
    w0 *= inv; w1 *= inv; w2 *= inv;

    const float4* x0 = (const float4*)(x + (size_t)i0 * C_IN);
    const float4* x1 = (const float4*)(x + (size_t)i1 * C_IN);
    const float4* x2 = (const float4*)(x + (size_t)i2 * C_IN);
    const float4* xs = (const float4*)(x_skip + (size_t)m * C_SKIP);
    float4* f = (float4*)(g_feat + (size_t)m * C_CAT);

    #pragma unroll
    for (int t = 0; t < 2; t++) {
        int c = lane + 32 * t;           // 0..63 float4 = 256 ch
        float4 a = x0[c], b = x1[c], d = x2[c];
        float4 r;
        r.x = w0 * a.x + w1 * b.x + w2 * d.x;
        r.y = w0 * a.y + w1 * b.y + w2 * d.y;
        r.z = w0 * a.z + w1 * b.z + w2 * d.z;
        r.w = w0 * a.w + w1 * b.w + w2 * d.w;
        f[c] = r;
    }
    f[64 + lane] = xs[lane];             // 32 float4 = 128 skip ch
}

// ---------------------------------------------------------------------------
// Kernel 3/4: tiled SGEMM  C = relu?(A[M,K] @ B[K,N] + bias)
// BM=BN=128, BK=16, 256 threads, 8x8 per thread, float4 smem traffic.
// ---------------------------------------------------------------------------
template <int KDIM, bool RELU>
__global__ void __launch_bounds__(256)
gemm_kernel(const float* __restrict__ A,
            const float* __restrict__ B,
            const float* __restrict__ bias,
            float* __restrict__ C,
            int Ncols) {
    const int BM = 128, BN = 128, BK = 16;
    __shared__ float As[BK][BM + 4];   // pad 4: float4-aligned rows, reduced store conflicts
    __shared__ float Bs[BK][BN + 4];

    int tid = threadIdx.x;
    int row0 = blockIdx.x * BM;
    int col0 = blockIdx.y * BN;
    int ty = tid >> 4;          // 0..15 -> rows ty*8
    int tx = tid & 15;          // 0..15 -> cols tx*8

    // A-tile load mapping: float4 f in [0,512): a_r=f/4 (row 0..127), a_k=(f%4)*4
    int af0 = tid, af1 = tid + 256;
    int ar0 = af0 >> 2, ak0 = (af0 & 3) * 4;
    int ar1 = af1 >> 2, ak1 = (af1 & 3) * 4;
    // B-tile: float4 f in [0,512): b_k=f/32, b_n=(f%32)*4
    int bk0 = af0 >> 5, bn0 = (af0 & 31) * 4;
    int bk1 = af1 >> 5, bn1 = (af1 & 31) * 4;

    float acc[8][8];
    #pragma unroll
    for (int i = 0; i < 8; i++)
        #pragma unroll
        for (int j = 0; j < 8; j++) acc[i][j] = 0.f;

    for (int k0 = 0; k0 < KDIM; k0 += BK) {
        float4 a0 = *(const float4*)&A[(size_t)(row0 + ar0) * KDIM + k0 + ak0];
        float4 a1 = *(const float4*)&A[(size_t)(row0 + ar1) * KDIM + k0 + ak1];
        float4 bv0 = *(const float4*)&B[(size_t)(k0 + bk0) * Ncols + col0 + bn0];
        float4 bv1 = *(const float4*)&B[(size_t)(k0 + bk1) * Ncols + col0 + bn1];

        __syncthreads();
        As[ak0 + 0][ar0] = a0.x; As[ak0 + 1][ar0] = a0.y;
        As[ak0 + 2][ar0] = a0.z; As[ak0 + 3][ar0] = a0.w;
        As[ak1 + 0][ar1] = a1.x; As[ak1 + 1][ar1] = a1.y;
        As[ak1 + 2][ar1] = a1.z; As[ak1 + 3][ar1] = a1.w;
        *(float4*)&Bs[bk0][bn0] = bv0;
        *(float4*)&Bs[bk1][bn1] = bv1;
        __syncthreads();

        #pragma unroll
        for (int kk = 0; kk < BK; kk++) {
            float4 fa0 = *(const float4*)&As[kk][ty * 8 + 0];
            float4 fa1 = *(const float4*)&As[kk][ty * 8 + 4];
            float4 fb0 = *(const float4*)&Bs[kk][tx * 8 + 0];
            float4 fb1 = *(const float4*)&Bs[kk][tx * 8 + 4];
            float a[8] = {fa0.x, fa0.y, fa0.z, fa0.w, fa1.x, fa1.y, fa1.z, fa1.w};
            float b[8] = {fb0.x, fb0.y, fb0.z, fb0.w, fb1.x, fb1.y, fb1.z, fb1.w};
            #pragma unroll
            for (int i = 0; i < 8; i++)
                #pragma unroll
                for (int j = 0; j < 8; j++)
                    acc[i][j] = fmaf(a[i], b[j], acc[i][j]);
        }
    }

    #pragma unroll
    for (int i = 0; i < 8; i++) {
        int r = row0 + ty * 8 + i;
        #pragma unroll
        for (int j = 0; j < 8; j += 4) {
            int cidx = col0 + tx * 8 + j;
            float4 v;
            v.x = acc[i][j + 0] + bias[cidx + 0];
            v.y = acc[i][j + 1] + bias[cidx + 1];
            v.z = acc[i][j + 2] + bias[cidx + 2];
            v.w = acc[i][j + 3] + bias[cidx + 3];
            if (RELU) {
                v.x = fmaxf(v.x, 0.f); v.y = fmaxf(v.y, 0.f);
                v.z = fmaxf(v.z, 0.f); v.w = fmaxf(v.w, 0.f);
            }
            *(float4*)&C[(size_t)r * Ncols + cidx] = v;
        }
    }
}

// ---------------------------------------------------------------------------
// Kernel 5: tail of output — copy pos_skip, zero the batch segment
// ---------------------------------------------------------------------------
__global__ void tail_kernel(const float* __restrict__ pos_skip,
                            float* __restrict__ out, int out_size) {
    const int base = M_PTS * H_DIM;
    for (int i = base + blockIdx.x * blockDim.x + threadIdx.x; i < out_size;
         i += gridDim.x * blockDim.x) {
        int r = i - base;
        out[i] = (r < M_PTS * 3) ? pos_skip[r] : 0.f;
    }
}

// ---------------------------------------------------------------------------
extern "C" void kernel_launch(void* const* d_in, const int* in_sizes, int n_in,
                              void* d_out, int out_size) {
    const float* x        = (const float*)d_in[0];
    const float* pos      = (const float*)d_in[1];
    const float* x_skip   = (const float*)d_in[3];
    const float* pos_skip = (const float*)d_in[4];
    const float* W1 = (const float*)d_in[6];
    const float* b1 = (const float*)d_in[7];
    const float* W2 = (const float*)d_in[8];
    const float* b2 = (const float*)d_in[9];
    float* out = (float*)d_out;

    // 1) kNN: 512 blocks x 256 threads (8 threads per query)
    knn_kernel<<<M_PTS / QPB, QPB * TPQ>>>(pos, pos_skip);

    // 2) interpolate + concat (warp per row)
    interp_kernel<<<(M_PTS * 32) / 256, 256>>>(x, x_skip);

    float* feat;  cudaGetSymbolAddress((void**)&feat, g_feat);
    float* h;     cudaGetSymbolAddress((void**)&h, g_h);

    // 3) GEMM1 + ReLU: [M,384] @ [384,256] -> g_h
    {
        dim3 grid(M_PTS / 128, H_DIM / 128);
        gemm_kernel<C_CAT, true><<<grid, 256>>>(feat, W1, b1, h, H_DIM);
        // 4) GEMM2: [M,256] @ [256,256] -> out[0 : M*256]
        gemm_kernel<H_DIM, false><<<grid, 256>>>(h, W2, b2, out, H_DIM);
    }

    // 5) tail
    tail_kernel<<<256, 256>>>(pos_skip, out, out_size);
}

// round 5
// speedup vs baseline: 1.6308x; 1.0359x over previous
#include <cuda_runtime.h>
#include <cuda_bf16.h>
#include <cstdint>

#define N_PTS  4096
#define M_PTS  16384
#define C_IN   256
#define C_SKIP 128
#define C_CAT  384
#define H_DIM  256

// Scratch (device globals — no runtime allocation allowed)
__device__ float g_feat[M_PTS * C_CAT];   // [M, 384] concat(y, x_skip)
__device__ float g_h[M_PTS * H_DIM];      // [M, 256] hidden
__device__ int   g_idx[M_PTS * 3];
__device__ float g_w[M_PTS * 4];          // w0,w1,w2, 1/(w0+w1+w2)

// ---------------------------------------------------------------------------
// Kernel 1: brute-force kNN (k=3). 8 threads per query, 32 queries per block.
// ---------------------------------------------------------------------------
#define KNN_TILE 1024
#define QPB 32
#define TPQ 8
__global__ void knn_kernel(const float* __restrict__ pos,
                           const float* __restrict__ pos_skip) {
    __shared__ float sx[KNN_TILE], sy[KNN_TILE], sz[KNN_TILE];
    __shared__ float pd[QPB][TPQ][3];
    __shared__ int   pi[QPB][TPQ][3];

    int qi = threadIdx.x / TPQ;
    int ts = threadIdx.x % TPQ;
    int m  = blockIdx.x * QPB + qi;

    float qx = pos_skip[3 * m + 0];
    float qy = pos_skip[3 * m + 1];
    float qz = pos_skip[3 * m + 2];

    float d0 = 1e30f, d1 = 1e30f, d2 = 1e30f;
    int   i0 = 0, i1 = 0, i2 = 0;

    for (int base = 0; base < N_PTS; base += KNN_TILE) {
        __syncthreads();
        for (int j = threadIdx.x; j < KNN_TILE; j += blockDim.x) {
            sx[j] = pos[3 * (base + j) + 0];
            sy[j] = pos[3 * (base + j) + 1];
            sz[j] = pos[3 * (base + j) + 2];
        }
        __syncthreads();
        #pragma unroll 8
        for (int j = ts; j < KNN_TILE; j += TPQ) {
            float dx = qx - sx[j];
            float dy = qy - sy[j];
            float dz = qz - sz[j];
            float d = fmaf(dx, dx, fmaf(dy, dy, dz * dz));
            int gi = base + j;
            if (d < d2) {
                if (d < d1) {
                    d2 = d1; i2 = i1;
                    if (d < d0) { d1 = d0; i1 = i0; d0 = d; i0 = gi; }
                    else        { d1 = d;  i1 = gi; }
                } else { d2 = d; i2 = gi; }
            }
        }
    }

    pd[qi][ts][0] = d0; pd[qi][ts][1] = d1; pd[qi][ts][2] = d2;
    pi[qi][ts][0] = i0; pi[qi][ts][1] = i1; pi[qi][ts][2] = i2;
    __syncthreads();

    if (ts == 0) {
        float b0 = 1e30f, b1 = 1e30f, b2 = 1e30f;
        int   j0 = 0, j1 = 0, j2 = 0;
        #pragma unroll
        for (int t = 0; t < TPQ; t++) {
            #pragma unroll
            for (int s = 0; s < 3; s++) {
                float d = pd[qi][t][s];
                int   gi = pi[qi][t][s];
                if (d < b2) {
                    if (d < b1) {
                        b2 = b1; j2 = j1;
                        if (d < b0) { b1 = b0; j1 = j0; b0 = d; j0 = gi; }
                        else        { b1 = d;  j1 = gi; }
                    } else { b2 = d; j2 = gi; }
                }
            }
        }
        float w0 = 1.f / fmaxf(b0, 1e-16f);
        float w1 = 1.f / fmaxf(b1, 1e-16f);
        float w2 = 1.f / fmaxf(b2, 1e-16f);
        g_idx[3 * m + 0] = j0;
        g_idx[3 * m + 1] = j1;
        g_idx[3 * m + 2] = j2;
        g_w[4 * m + 0] = w0;
        g_w[4 * m + 1] = w1;
        g_w[4 * m + 2] = w2;
        g_w[4 * m + 3] = 1.f / (w0 + w1 + w2);
    }
}

// ---------------------------------------------------------------------------
// Kernel 2: interpolate + concat -> g_feat [M, 384]. One warp per row, float4.
// ---------------------------------------------------------------------------
__global__ void interp_kernel(const float* __restrict__ x,
                              const float* __restrict__ x_skip) {
    int warp = (blockIdx.x * blockDim.x + threadIdx.x) >> 5;
    int lane = threadIdx.x & 31;
    if (warp >= M_PTS) return;
    int m = warp;

    int i0 = g_idx[3 * m + 0];
    int i1 = g_idx[3 * m + 1];
    int i2 = g_idx[3 * m + 2];
    float w0 = g_w[4 * m + 0];
    float w1 = g_w[4 * m + 1];
    float w2 = g_w[4 * m + 2];
    float inv = g_w[4 * m + 3];
    w0 *= inv; w1 *= inv; w2 *= inv;

    const float4* x0 = (const float4*)(x + (size_t)i0 * C_IN);
    const float4* x1 = (const float4*)(x + (size_t)i1 * C_IN);
    const float4* x2 = (const float4*)(x + (size_t)i2 * C_IN);
    const float4* xs = (const float4*)(x_skip + (size_t)m * C_SKIP);
    float4* f = (float4*)(g_feat + (size_t)m * C_CAT);

    #pragma unroll
    for (int t = 0; t < 2; t++) {
        int c = lane + 32 * t;
        float4 a = x0[c], b = x1[c], d = x2[c];
        float4 r;
        r.x = w0 * a.x + w1 * b.x + w2 * d.x;
        r.y = w0 * a.y + w1 * b.y + w2 * d.y;
        r.z = w0 * a.z + w1 * b.z + w2 * d.z;
        r.w = w0 * a.w + w1 * b.w + w2 * d.w;
        f[c] = r;
    }
    f[64 + lane] = xs[lane];
}

// ---------------------------------------------------------------------------
// Kernel 3/4: tensor-core GEMM via 3xBF16 split (fp32-accurate).
//   C = relu?(A[M,K] @ B[K,N] + bias)
// BM=128, BN=64, BK=32. 256 threads = 8 warps (4m x 2n), warp tile 32x32.
// mma.sync.m16n8k16.bf16; each product computed as ah*bh + ah*bl + al*bh.
// ---------------------------------------------------------------------------
#define MMA_BF16(acc, a, b)                                                   \
    asm volatile(                                                             \
        "mma.sync.aligned.m16n8k16.row.col.f32.bf16.bf16.f32 "                \
        "{%0,%1,%2,%3},{%4,%5,%6,%7},{%8,%9},{%0,%1,%2,%3};"                  \
        : "+f"((acc)[0]), "+f"((acc)[1]), "+f"((acc)[2]), "+f"((acc)[3])      \
        : "r"((a)[0]), "r"((a)[1]), "r"((a)[2]), "r"((a)[3]),                 \
          "r"((b)[0]), "r"((b)[1]))

__device__ __forceinline__ void split2bf(float v, __nv_bfloat16& hi,
                                         __nv_bfloat16& lo) {
    hi = __float2bfloat16(v);
    lo = __float2bfloat16(v - __bfloat162float(hi));
}

template <int KDIM, bool RELU>
__global__ void __launch_bounds__(256, 2)
gemm_bf16x3_kernel(const float* __restrict__ A, const float* __restrict__ B,
                   const float* __restrict__ bias, float* __restrict__ C,
                   int Ncols) {
    const int BM = 128, BN = 64, BK = 32, AS = BK + 8;   // 40-elem stride
    __shared__ __nv_bfloat16 Ah[BM][AS], Al[BM][AS];
    __shared__ __nv_bfloat16 Bh[BN][AS], Bl[BN][AS];

    int tid  = threadIdx.x;
    int row0 = blockIdx.x * BM;
    int col0 = blockIdx.y * BN;
    int w    = tid >> 5, lane = tid & 31;
    int wm   = w & 3, wn = w >> 2;        // 4 m-warps x 2 n-warps
    int g    = lane >> 2, tq = lane & 3;  // mma lane decomposition

    float acc[2][4][4];
    #pragma unroll
    for (int mt = 0; mt < 2; mt++)
        #pragma unroll
        for (int nt = 0; nt < 4; nt++)
            #pragma unroll
            for (int i = 0; i < 4; i++) acc[mt][nt][i] = 0.f;

    for (int k0 = 0; k0 < KDIM; k0 += BK) {
        // Prefetch global tiles into registers
        float4 av[4], bv[2];
        #pragma unroll
        for (int l = 0; l < 4; l++) {
            int f = tid + l * 256;                  // 1024 float4 of A tile
            int r = f >> 3, kq = (f & 7) * 4;
            av[l] = *(const float4*)&A[(size_t)(row0 + r) * KDIM + k0 + kq];
        }
        #pragma unroll
        for (int l = 0; l < 2; l++) {
            int f = tid + l * 256;                  // 512 float4 of B tile
            int kr = f >> 4, nq = (f & 15) * 4;
            bv[l] = *(const float4*)&B[(size_t)(k0 + kr) * Ncols + col0 + nq];
        }

        __syncthreads();   // previous compute done before overwrite

        #pragma unroll
        for (int l = 0; l < 4; l++) {
            int f = tid + l * 256;
            int r = f >> 3, kq = (f & 7) * 4;
            float e[4] = {av[l].x, av[l].y, av[l].z, av[l].w};
            #pragma unroll
            for (int i = 0; i < 4; i++) {
                __nv_bfloat16 hi, lo;
                split2bf(e[i], hi, lo);
                Ah[r][kq + i] = hi;
                Al[r][kq + i] = lo;
            }
        }
        #pragma unroll
        for (int l = 0; l < 2; l++) {
            int f = tid + l * 256;
            int kr = f >> 4, nq = (f & 15) * 4;
            float e[4] = {bv[l].x, bv[l].y, bv[l].z, bv[l].w};
            #pragma unroll
            for (int i = 0; i < 4; i++) {          // transpose: Bs[n][k]
                __nv_bfloat16 hi, lo;
                split2bf(e[i], hi, lo);
                Bh[nq + i][kr] = hi;
                Bl[nq + i][kr] = lo;
            }
        }
        __syncthreads();

        #pragma unroll
        for (int ks = 0; ks < BK; ks += 16) {
            uint32_t ah[2][4], al[2][4], bh[4][2], bl[4][2];
            #pragma unroll
            for (int mt = 0; mt < 2; mt++) {
                int mb = wm * 32 + mt * 16;
                ah[mt][0] = *(const uint32_t*)&Ah[mb + g][ks + 2 * tq];
                ah[mt][1] = *(const uint32_t*)&Ah[mb + g + 8][ks + 2 * tq];
                ah[mt][2] = *(const uint32_t*)&Ah[mb + g][ks + 2 * tq + 8];
                ah[mt][3] = *(const uint32_t*)&Ah[mb + g + 8][ks + 2 * tq + 8];
                al[mt][0] = *(const uint32_t*)&Al[mb + g][ks + 2 * tq];
                al[mt][1] = *(const uint32_t*)&Al[mb + g + 8][ks + 2 * tq];
                al[mt][2] = *(const uint32_t*)&Al[mb + g][ks + 2 * tq + 8];
                al[mt][3] = *(const uint32_t*)&Al[mb + g + 8][ks + 2 * tq + 8];
            }
            #pragma unroll
            for (int nt = 0; nt < 4; nt++) {
                int nb = wn * 32 + nt * 8 + g;
                bh[nt][0] = *(const uint32_t*)&Bh[nb][ks + 2 * tq];
                bh[nt][1] = *(const uint32_t*)&Bh[nb][ks + 2 * tq + 8];
                bl[nt][0] = *(const uint32_t*)&Bl[nb][ks + 2 * tq];
                bl[nt][1] = *(const uint32_t*)&Bl[nb][ks + 2 * tq + 8];
            }
            #pragma unroll
            for (int mt = 0; mt < 2; mt++)
                #pragma unroll
                for (int nt = 0; nt < 4; nt++) {
                    MMA_BF16(acc[mt][nt], ah[mt], bh[nt]);   // hi*hi
                    MMA_BF16(acc[mt][nt], ah[mt], bl[nt]);   // hi*lo
                    MMA_BF16(acc[mt][nt], al[mt], bh[nt]);   // lo*hi
                }
        }
    }

    // Epilogue: bias + optional relu, float2 stores
    #pragma unroll
    for (int mt = 0; mt < 2; mt++) {
        int r0 = row0 + wm * 32 + mt * 16 + g;
        #pragma unroll
        for (int nt = 0; nt < 4; nt++) {
            int c = col0 + wn * 32 + nt * 8 + 2 * tq;
            float bx = bias[c], by = bias[c + 1];
            float2 v0, v1;
            v0.x = acc[mt][nt][0] + bx;  v0.y = acc[mt][nt][1] + by;
            v1.x = acc[mt][nt][2] + bx;  v1.y = acc[mt][nt][3] + by;
            if (RELU) {
                v0.x = fmaxf(v0.x, 0.f); v0.y = fmaxf(v0.y, 0.f);
                v1.x = fmaxf(v1.x, 0.f); v1.y = fmaxf(v1.y, 0.f);
            }
            *(float2*)&C[(size_t)r0 * Ncols + c]       = v0;
            *(float2*)&C[(size_t)(r0 + 8) * Ncols + c] = v1;
        }
    }
}

// ---------------------------------------------------------------------------
// Kernel 5: tail of output — copy pos_skip, zero the batch segment
// ---------------------------------------------------------------------------
__global__ void tail_kernel(const float* __restrict__ pos_skip,
                            float* __restrict__ out, int out_size) {
    const int base = M_PTS * H_DIM;
    for (int i = base + blockIdx.x * blockDim.x + threadIdx.x; i < out_size;
         i += gridDim.x * blockDim.x) {
        int r = i - base;
        out[i] = (r < M_PTS * 3) ? pos_skip[r] : 0.f;
    }
}

// ---------------------------------------------------------------------------
extern "C" void kernel_launch(void* const* d_in, const int* in_sizes, int n_in,
                              void* d_out, int out_size) {
    const float* x        = (const float*)d_in[0];
    const float* pos      = (const float*)d_in[1];
    const float* x_skip   = (const float*)d_in[3];
    const float* pos_skip = (const float*)d_in[4];
    const float* W1 = (const float*)d_in[6];
    const float* b1 = (const float*)d_in[7];
    const float* W2 = (const float*)d_in[8];
    const float* b2 = (const float*)d_in[9];
    float* out = (float*)d_out;

    // 1) kNN
    knn_kernel<<<M_PTS / QPB, QPB * TPQ>>>(pos, pos_skip);

    // 2) interpolate + concat
    interp_kernel<<<(M_PTS * 32) / 256, 256>>>(x, x_skip);

    float* feat;  cudaGetSymbolAddress((void**)&feat, g_feat);
    float* h;     cudaGetSymbolAddress((void**)&h, g_h);

    // 3) GEMM1 + ReLU: [M,384] @ [384,256] -> g_h
    {
        dim3 grid(M_PTS / 128, H_DIM / 64);
        gemm_bf16x3_kernel<C_CAT, true><<<grid, 256>>>(feat, W1, b1, h, H_DIM);
        // 4) GEMM2: [M,256] @ [256,256] -> out[0 : M*256]
        gemm_bf16x3_kernel<H_DIM, false><<<grid, 256>>>(h, W2, b2, out, H_DIM);
    }

    // 5) tail
    tail_kernel<<<256, 256>>>(pos_skip, out, out_size);
}

// round 6
// speedup vs baseline: 2.2379x; 1.3723x over previous
#include <cuda_runtime.h>
#include <cuda_bf16.h>
#include <cstdint>

#define N_PTS  4096
#define M_PTS  16384
#define C_IN   256
#define C_SKIP 128
#define C_CAT  384
#define H_DIM  256

// Scratch (device globals — no runtime allocation allowed)
__device__ __align__(16) __nv_bfloat16 g_fh[M_PTS * C_CAT];  // feat hi
__device__ __align__(16) __nv_bfloat16 g_fl[M_PTS * C_CAT];  // feat lo
__device__ __align__(16) __nv_bfloat16 g_hh[M_PTS * H_DIM];  // hidden hi
__device__ __align__(16) __nv_bfloat16 g_hl[M_PTS * H_DIM];  // hidden lo
__device__ __align__(16) __nv_bfloat16 g_w1h[C_CAT * H_DIM], g_w1l[C_CAT * H_DIM];
__device__ __align__(16) __nv_bfloat16 g_w2h[H_DIM * H_DIM], g_w2l[H_DIM * H_DIM];
__device__ int   g_idx[M_PTS * 3];
__device__ float g_w[M_PTS * 4];

// ---------------------------------------------------------------------------
// Kernel 1: brute-force kNN (k=3). 8 threads per query, 32 queries per block.
// ---------------------------------------------------------------------------
#define KNN_TILE 1024
#define QPB 32
#define TPQ 8
__global__ void knn_kernel(const float* __restrict__ pos,
                           const float* __restrict__ pos_skip) {
    __shared__ float sx[KNN_TILE], sy[KNN_TILE], sz[KNN_TILE];
    __shared__ float pd[QPB][TPQ][3];
    __shared__ int   pi[QPB][TPQ][3];

    int qi = threadIdx.x / TPQ;
    int ts = threadIdx.x % TPQ;
    int m  = blockIdx.x * QPB + qi;

    float qx = pos_skip[3 * m + 0];
    float qy = pos_skip[3 * m + 1];
    float qz = pos_skip[3 * m + 2];

    float d0 = 1e30f, d1 = 1e30f, d2 = 1e30f;
    int   i0 = 0, i1 = 0, i2 = 0;

    for (int base = 0; base < N_PTS; base += KNN_TILE) {
        __syncthreads();
        for (int j = threadIdx.x; j < KNN_TILE; j += blockDim.x) {
            sx[j] = pos[3 * (base + j) + 0];
            sy[j] = pos[3 * (base + j) + 1];
            sz[j] = pos[3 * (base + j) + 2];
        }
        __syncthreads();
        #pragma unroll 8
        for (int j = ts; j < KNN_TILE; j += TPQ) {
            float dx = qx - sx[j];
            float dy = qy - sy[j];
            float dz = qz - sz[j];
            float d = fmaf(dx, dx, fmaf(dy, dy, dz * dz));
            int gi = base + j;
            if (d < d2) {
                if (d < d1) {
                    d2 = d1; i2 = i1;
                    if (d < d0) { d1 = d0; i1 = i0; d0 = d; i0 = gi; }
                    else        { d1 = d;  i1 = gi; }
                } else { d2 = d; i2 = gi; }
            }
        }
    }

    pd[qi][ts][0] = d0; pd[qi][ts][1] = d1; pd[qi][ts][2] = d2;
    pi[qi][ts][0] = i0; pi[qi][ts][1] = i1; pi[qi][ts][2] = i2;
    __syncthreads();

    if (ts == 0) {
        float b0 = 1e30f, b1 = 1e30f, b2 = 1e30f;
        int   j0 = 0, j1 = 0, j2 = 0;
        #pragma unroll
        for (int t = 0; t < TPQ; t++) {
            #pragma unroll
            for (int s = 0; s < 3; s++) {
                float d = pd[qi][t][s];
                int   gi = pi[qi][t][s];
                if (d < b2) {
                    if (d < b1) {
                        b2 = b1; j2 = j1;
                        if (d < b0) { b1 = b0; j1 = j0; b0 = d; j0 = gi; }
                        else        { b1 = d;  j1 = gi; }
                    } else { b2 = d; j2 = gi; }
                }
            }
        }
        float w0 = 1.f / fmaxf(b0, 1e-16f);
        float w1 = 1.f / fmaxf(b1, 1e-16f);
        float w2 = 1.f / fmaxf(b2, 1e-16f);
        g_idx[3 * m + 0] = j0;
        g_idx[3 * m + 1] = j1;
        g_idx[3 * m + 2] = j2;
        g_w[4 * m + 0] = w0;
        g_w[4 * m + 1] = w1;
        g_w[4 * m + 2] = w2;
        g_w[4 * m + 3] = 1.f / (w0 + w1 + w2);
    }
}

// ---------------------------------------------------------------------------
// Helpers: fp32 -> (bf16 hi, bf16 lo residual)
// ---------------------------------------------------------------------------
__device__ __forceinline__ void split2bf(float v, __nv_bfloat16& hi,
                                         __nv_bfloat16& lo) {
    hi = __float2bfloat16(v);
    lo = __float2bfloat16(v - __bfloat162float(hi));
}
__device__ __forceinline__ uint32_t pack2(__nv_bfloat16 a, __nv_bfloat16 b) {
    uint32_t r;
    __nv_bfloat162 t(a, b);
    r = *(uint32_t*)&t;
    return r;
}

// ---------------------------------------------------------------------------
// Kernel 2: interpolate + concat -> split bf16 feat [M,384]. Warp per row.
// ---------------------------------------------------------------------------
__global__ void interp_kernel(const float* __restrict__ x,
                              const float* __restrict__ x_skip) {
    int warp = (blockIdx.x * blockDim.x + threadIdx.x) >> 5;
    int lane = threadIdx.x & 31;
    if (warp >= M_PTS) return;
    int m = warp;

    int i0 = g_idx[3 * m + 0];
    int i1 = g_idx[3 * m + 1];
    int i2 = g_idx[3 * m + 2];
    float w0 = g_w[4 * m + 0];
    float w1 = g_w[4 * m + 1];
    float w2 = g_w[4 * m + 2];
    float inv = g_w[4 * m + 3];
    w0 *= inv; w1 *= inv; w2 *= inv;

    const float2* x0 = (const float2*)(x + (size_t)i0 * C_IN);
    const float2* x1 = (const float2*)(x + (size_t)i1 * C_IN);
    const float2* x2 = (const float2*)(x + (size_t)i2 * C_IN);
    const float2* xs = (const float2*)(x_skip + (size_t)m * C_SKIP);
    uint32_t* fh = (uint32_t*)(g_fh + (size_t)m * C_CAT);
    uint32_t* fl = (uint32_t*)(g_fl + (size_t)m * C_CAT);

    #pragma unroll
    for (int p = lane; p < 192; p += 32) {       // 192 bf16-pairs per row
        float v0, v1;
        if (p < 128) {
            float2 a = x0[p], b = x1[p], d = x2[p];
            v0 = w0 * a.x + w1 * b.x + w2 * d.x;
            v1 = w0 * a.y + w1 * b.y + w2 * d.y;
        } else {
            float2 s = xs[p - 128];
            v0 = s.x; v1 = s.y;
        }
        __nv_bfloat16 h0, l0, h1, l1;
        split2bf(v0, h0, l0);
        split2bf(v1, h1, l1);
        fh[p] = pack2(h0, h1);
        fl[p] = pack2(l0, l1);
    }
}

// ---------------------------------------------------------------------------
// Kernel 2b: split weights W1, W2 into bf16 hi/lo
// ---------------------------------------------------------------------------
__global__ void split_w_kernel(const float* __restrict__ W1,
                               const float* __restrict__ W2) {
    int i = blockIdx.x * blockDim.x + threadIdx.x;
    const int NW1 = C_CAT * H_DIM;
    const int NW2 = H_DIM * H_DIM;
    if (i < NW1) {
        __nv_bfloat16 h, l;
        split2bf(W1[i], h, l);
        g_w1h[i] = h; g_w1l[i] = l;
    } else if (i < NW1 + NW2) {
        int j = i - NW1;
        __nv_bfloat16 h, l;
        split2bf(W2[j], h, l);
        g_w2h[j] = h; g_w2l[j] = l;
    }
}

// ---------------------------------------------------------------------------
// Tensor-core GEMM, 3xBF16 compensated, ldmatrix + double-buffered smem.
//   C[M,256] = relu?(A[M,K] @ B[K,256] + bias)
// BM=128, BN=64, BK=16; 8 warps (4m x 2n), warp tile 32x32.
// ---------------------------------------------------------------------------
#define MMA_BF16(acc, a, b)                                                   \
    asm volatile(                                                             \
        "mma.sync.aligned.m16n8k16.row.col.f32.bf16.bf16.f32 "                \
        "{%0,%1,%2,%3},{%4,%5,%6,%7},{%8,%9},{%0,%1,%2,%3};"                  \
        : "+f"((acc)[0]), "+f"((acc)[1]), "+f"((acc)[2]), "+f"((acc)[3])      \
        : "r"((a)[0]), "r"((a)[1]), "r"((a)[2]), "r"((a)[3]),                 \
          "r"((b)[0]), "r"((b)[1]))

__device__ __forceinline__ void ldsm_x4(uint32_t* r, uint32_t addr) {
    asm volatile(
        "ldmatrix.sync.aligned.m8n8.x4.shared.b16 {%0,%1,%2,%3},[%4];"
        : "=r"(r[0]), "=r"(r[1]), "=r"(r[2]), "=r"(r[3]) : "r"(addr));
}
__device__ __forceinline__ void ldsm_x4_t(uint32_t* r, uint32_t addr) {
    asm volatile(
        "ldmatrix.sync.aligned.m8n8.x4.trans.shared.b16 {%0,%1,%2,%3},[%4];"
        : "=r"(r[0]), "=r"(r[1]), "=r"(r[2]), "=r"(r[3]) : "r"(addr));
}

template <int KDIM, bool RELU, bool SPLIT_OUT>
__global__ void __launch_bounds__(256, 2)
gemm_bf16_tc(const __nv_bfloat16* __restrict__ Ahg,
             const __nv_bfloat16* __restrict__ Alg,
             const __nv_bfloat16* __restrict__ Bhg,
             const __nv_bfloat16* __restrict__ Blg,
             const float* __restrict__ bias,
             float* __restrict__ C,
             __nv_bfloat16* __restrict__ Ch,
             __nv_bfloat16* __restrict__ Cl) {
    const int BM = 128, BN = 64, BK = 16;
    const int ASTR = 24;   // bf16 elems per A smem row (48B: ldmatrix conflict-free)
    const int BSTR = 72;   // bf16 elems per B smem row (144B: conflict-free)
    const int NCOL = 256;

    __shared__ __align__(16) __nv_bfloat16 sAh[2][BM * ASTR];
    __shared__ __align__(16) __nv_bfloat16 sAl[2][BM * ASTR];
    __shared__ __align__(16) __nv_bfloat16 sBh[2][BK * BSTR];
    __shared__ __align__(16) __nv_bfloat16 sBl[2][BK * BSTR];

    int tid  = threadIdx.x;
    int lane = tid & 31;
    int w    = tid >> 5;
    int wm   = w & 3, wn = w >> 2;          // 4 m-warps x 2 n-warps
    int g    = lane >> 2, tq = lane & 3;
    int row0 = blockIdx.x * BM;
    int col0 = blockIdx.y * BN;

    // ldg mapping: A 512 uint4/stage (2/thread), B 256 uint4/stage (1/thread)
    int aArr = tid >> 7 & 1;                 // f=tid:   arr=(tid>>8)=0 ... use f-form below
    (void)aArr;
    // A: f in [0,512): arr=f>>8, r=(f&255)>>1, c=f&1
    int af0 = tid,       ar0 = (af0 & 255) >> 1, ac0 = af0 & 1;
    int af1 = tid + 256, ar1 = (af1 & 255) >> 1, ac1 = af1 & 1;
    int aarr0 = af0 >> 8, aarr1 = af1 >> 8;
    // B: f=tid in [0,256): arr=f>>7, k=(f&127)>>3, c=f&7
    int barr = tid >> 7, bk = (tid & 127) >> 3, bc = tid & 7;

    float acc[2][4][4];
    #pragma unroll
    for (int mt = 0; mt < 2; mt++)
        #pragma unroll
        for (int nt = 0; nt < 4; nt++)
            #pragma unroll
            for (int i = 0; i < 4; i++) acc[mt][nt][i] = 0.f;

    uint4 av0, av1, bv;
    auto ldg_stage = [&](int s) {
        int k0 = s * BK;
        const __nv_bfloat16* a0p = (aarr0 ? Alg : Ahg);
        const __nv_bfloat16* a1p = (aarr1 ? Alg : Ahg);
        const __nv_bfloat16* bp  = (barr  ? Blg : Bhg);
        av0 = *(const uint4*)(a0p + (size_t)(row0 + ar0) * KDIM + k0 + 8 * ac0);
        av1 = *(const uint4*)(a1p + (size_t)(row0 + ar1) * KDIM + k0 + 8 * ac1);
        bv  = *(const uint4*)(bp + (size_t)(k0 + bk) * NCOL + col0 + 8 * bc);
    };
    auto sts_stage = [&](int buf) {
        __nv_bfloat16* a0d = (aarr0 ? sAl[buf] : sAh[buf]);
        __nv_bfloat16* a1d = (aarr1 ? sAl[buf] : sAh[buf]);
        __nv_bfloat16* bd  = (barr  ? sBl[buf] : sBh[buf]);
        *(uint4*)(a0d + ar0 * ASTR + 8 * ac0) = av0;
        *(uint4*)(a1d + ar1 * ASTR + 8 * ac1) = av1;
        *(uint4*)(bd + bk * BSTR + 8 * bc) = bv;
    };

    // ldmatrix lane addressing (bytes)
    int aRow = lane & 15, aHalf = lane >> 4;            // A: row, k-half
    int aOffB = aRow * ASTR * 2 + 16 * aHalf;           // within one mt tile base
    int bOffB = (lane & 15) * BSTR * 2 +
                (wn * 32 + 8 * (lane >> 4)) * 2;        // + p*32B for pair p

    const int NSTAGE = KDIM / BK;
    ldg_stage(0);
    sts_stage(0);
    __syncthreads();

    for (int s = 0; s < NSTAGE; s++) {
        int buf = s & 1;
        if (s + 1 < NSTAGE) ldg_stage(s + 1);

        uint32_t baseAh = (uint32_t)__cvta_generic_to_shared(sAh[buf]);
        uint32_t baseAl = (uint32_t)__cvta_generic_to_shared(sAl[buf]);
        uint32_t baseBh = (uint32_t)__cvta_generic_to_shared(sBh[buf]);
        uint32_t baseBl = (uint32_t)__cvta_generic_to_shared(sBl[buf]);

        uint32_t ah[2][4], al[2][4], bh[4][2], bl[4][2];
        #pragma unroll
        for (int mt = 0; mt < 2; mt++) {
            uint32_t off = (wm * 32 + mt * 16) * ASTR * 2 + aOffB;
            ldsm_x4(ah[mt], baseAh + off);
            ldsm_x4(al[mt], baseAl + off);
        }
        #pragma unroll
        for (int p = 0; p < 2; p++) {
            uint32_t off = bOffB + p * 32;   // +16 elems = 32B in n
            uint32_t r[4];
            ldsm_x4_t(r, baseBh + off);
            bh[2 * p][0] = r[0]; bh[2 * p][1] = r[1];
            bh[2 * p + 1][0] = r[2]; bh[2 * p + 1][1] = r[3];
            ldsm_x4_t(r, baseBl + off);
            bl[2 * p][0] = r[0]; bl[2 * p][1] = r[1];
            bl[2 * p + 1][0] = r[2]; bl[2 * p + 1][1] = r[3];
        }

        #pragma unroll
        for (int mt = 0; mt < 2; mt++)
            #pragma unroll
            for (int nt = 0; nt < 4; nt++) {
                MMA_BF16(acc[mt][nt], ah[mt], bh[nt]);   // hi*hi
                MMA_BF16(acc[mt][nt], ah[mt], bl[nt]);   // hi*lo
                MMA_BF16(acc[mt][nt], al[mt], bh[nt]);   // lo*hi
            }

        if (s + 1 < NSTAGE) {
            sts_stage((s + 1) & 1);
            __syncthreads();
        }
    }

    // Epilogue
    #pragma unroll
    for (int mt = 0; mt < 2; mt++) {
        int r0 = row0 + wm * 32 + mt * 16 + g;
        #pragma unroll
        for (int nt = 0; nt < 4; nt++) {
            int c = col0 + wn * 32 + nt * 8 + 2 * tq;
            float bx = bias[c], by = bias[c + 1];
            float2 v0, v1;
            v0.x = acc[mt][nt][0] + bx;  v0.y = acc[mt][nt][1] + by;
            v1.x = acc[mt][nt][2] + bx;  v1.y = acc[mt][nt][3] + by;
            if (RELU) {
                v0.x = fmaxf(v0.x, 0.f); v0.y = fmaxf(v0.y, 0.f);
                v1.x = fmaxf(v1.x, 0.f); v1.y = fmaxf(v1.y, 0.f);
            }
            if (SPLIT_OUT) {
                __nv_bfloat16 h0, l0, h1, l1;
                split2bf(v0.x, h0, l0); split2bf(v0.y, h1, l1);
                *(uint32_t*)&Ch[(size_t)r0 * NCOL + c] = pack2(h0, h1);
                *(uint32_t*)&Cl[(size_t)r0 * NCOL + c] = pack2(l0, l1);
                split2bf(v1.x, h0, l0); split2bf(v1.y, h1, l1);
                *(uint32_t*)&Ch[(size_t)(r0 + 8) * NCOL + c] = pack2(h0, h1);
                *(uint32_t*)&Cl[(size_t)(r0 + 8) * NCOL + c] = pack2(l0, l1);
            } else {
                *(float2*)&C[(size_t)r0 * NCOL + c]       = v0;
                *(float2*)&C[(size_t)(r0 + 8) * NCOL + c] = v1;
            }
        }
    }
}

// ---------------------------------------------------------------------------
// Tail: copy pos_skip, zero the batch segment
// ---------------------------------------------------------------------------
__global__ void tail_kernel(const float* __restrict__ pos_skip,
                            float* __restrict__ out, int out_size) {
    const int base = M_PTS * H_DIM;
    for (int i = base + blockIdx.x * blockDim.x + threadIdx.x; i < out_size;
         i += gridDim.x * blockDim.x) {
        int r = i - base;
        out[i] = (r < M_PTS * 3) ? pos_skip[r] : 0.f;
    }
}

// ---------------------------------------------------------------------------
extern "C" void kernel_launch(void* const* d_in, const int* in_sizes, int n_in,
                              void* d_out, int out_size) {
    const float* x        = (const float*)d_in[0];
    const float* pos      = (const float*)d_in[1];
    const float* x_skip   = (const float*)d_in[3];
    const float* pos_skip = (const float*)d_in[4];
    const float* W1 = (const float*)d_in[6];
    const float* b1 = (const float*)d_in[7];
    const float* W2 = (const float*)d_in[8];
    const float* b2 = (const float*)d_in[9];
    float* out = (float*)d_out;

    // 1) weight split (independent) + kNN
    split_w_kernel<<<(C_CAT * H_DIM + H_DIM * H_DIM + 255) / 256, 256>>>(W1, W2);
    knn_kernel<<<M_PTS / QPB, QPB * TPQ>>>(pos, pos_skip);

    // 2) interpolate + concat -> split bf16 feat
    interp_kernel<<<(M_PTS * 32) / 256, 256>>>(x, x_skip);

    __nv_bfloat16 *fh, *fl, *hh, *hl, *w1h, *w1l, *w2h, *w2l;
    cudaGetSymbolAddress((void**)&fh, g_fh);
    cudaGetSymbolAddress((void**)&fl, g_fl);
    cudaGetSymbolAddress((void**)&hh, g_hh);
    cudaGetSymbolAddress((void**)&hl, g_hl);
    cudaGetSymbolAddress((void**)&w1h, g_w1h);
    cudaGetSymbolAddress((void**)&w1l, g_w1l);
    cudaGetSymbolAddress((void**)&w2h, g_w2h);
    cudaGetSymbolAddress((void**)&w2l, g_w2l);

    dim3 grid(M_PTS / 128, H_DIM / 64);
    // 3) GEMM1 + ReLU -> split hidden
    gemm_bf16_tc<C_CAT, true, true><<<grid, 256>>>(
        fh, fl, w1h, w1l, b1, nullptr, hh, hl);
    // 4) GEMM2 -> fp32 out
    gemm_bf16_tc<H_DIM, false, false><<<grid, 256>>>(
        hh, hl, w2h, w2l, b2, out, nullptr, nullptr);

    // 5) tail
    tail_kernel<<<256, 256>>>(pos_skip, out, out_size);
}